// round 15
// baseline (speedup 1.0000x reference)
#include <cuda_runtime.h>
#include <cstdint>

// CRF loss: inputs [1024,512,50] f32, transitions [50,50] f32,
// masks [1024,512] int32 (bool as i32), tag_indices [1024,512] i32.
// Output: [0] = loss scalar, [1..2500] = transitions passthrough.
// Strategy: persistent LPT queue; 4 warps per row (warps 0,1 fwd states
// 0-24/25-49; warps 2,3 bwd). Unified lockstep step loop, one
// __syncthreads per step, volatile m-relay, double-buffered p/m.

#define BSZ 1024
#define SLEN 512
#define NC 50
#define LOG2E 1.4426950408889634f
#define LN2   0.6931471805599453f
#define NBLK 5
#define GRID_MAIN (148 * NBLK)

typedef unsigned long long ull;

__device__ float g_partial[BSZ];
__device__ int g_len[BSZ];
__device__ int g_order[BSZ];
__device__ unsigned int g_head = 0;
__device__ unsigned int g_count = 0;

__device__ __forceinline__ ull ffma2(ull a, ull b, ull c) {
    ull d;
    asm("fma.rn.f32x2 %0, %1, %2, %3;" : "=l"(d) : "l"(a), "l"(b), "l"(c));
    return d;
}
__device__ __forceinline__ ull fadd2(ull a, ull b) {
    ull d;
    asm("add.rn.f32x2 %0, %1, %2;" : "=l"(d) : "l"(a), "l"(b));
    return d;
}
__device__ __forceinline__ ull pack2(float lo, float hi) {
    ull d;
    asm("mov.b64 %0, {%1, %2};" : "=l"(d) : "f"(lo), "f"(hi));
    return d;
}
__device__ __forceinline__ void unpack2(float& lo, float& hi, ull v) {
    asm("mov.b64 {%0, %1}, %2;" : "=f"(lo), "=f"(hi) : "l"(v));
}
__device__ __forceinline__ float ex2f(float a) {
    float r; asm("ex2.approx.ftz.f32 %0, %1;" : "=f"(r) : "f"(a)); return r;
}
__device__ __forceinline__ float lg2f(float a) {
    float r; asm("lg2.approx.ftz.f32 %0, %1;" : "=f"(r) : "f"(a)); return r;
}

// s = sum_{c=0..49} buf[c] * E[c]  (E packed over c pairs, 25 ull)
__device__ __forceinline__ float matvec50_1(
    const float* buf, const ull* E)
{
    const ulonglong2* pq = reinterpret_cast<const ulonglong2*>(buf);
    ull a0 = 0, a1 = 0, a2 = 0, a3 = 0;
    #pragma unroll
    for (int j = 0; j < 12; j += 2) {
        ulonglong2 v = pq[j];
        ulonglong2 w = pq[j + 1];
        a0 = ffma2(v.x, E[2 * j],     a0);
        a1 = ffma2(v.y, E[2 * j + 1], a1);
        a2 = ffma2(w.x, E[2 * j + 2], a2);
        a3 = ffma2(w.y, E[2 * j + 3], a3);
    }
    ull last = reinterpret_cast<const ull*>(buf)[24];
    a0 = ffma2(last, E[24], a0);
    a0 = fadd2(a0, a1);
    a2 = fadd2(a2, a3);
    a0 = fadd2(a0, a2);
    float lo, hi;
    unpack2(lo, hi, a0);
    return lo + hi;
}

// ---------- pre-pass 1: lengths + counter reset ----------
__global__ void __launch_bounds__(256) prep_len_kernel(
    const int* __restrict__ maskI)
{
    if (blockIdx.x == 0 && threadIdx.x == 0) { g_head = 0; g_count = 0; }
    int w = (blockIdx.x * blockDim.x + threadIdx.x) >> 5;   // global warp = row
    int lane = threadIdx.x & 31;
    if (w < BSZ) {
        const int4* m = reinterpret_cast<const int4*>(maskI + (size_t)w * SLEN);
        int s = 0;
        #pragma unroll
        for (int k = 0; k < 4; ++k) {
            int4 v = m[lane + 32 * k];
            s += v.x + v.y + v.z + v.w;
        }
        #pragma unroll
        for (int o = 16; o; o >>= 1)
            s += __shfl_xor_sync(0xffffffffu, s, o);
        if (lane == 0) g_len[w] = SLEN - s;   // monotone mask => [128,512]
    }
}

// ---------- pre-pass 2: counting sort by length, descending ----------
__global__ void __launch_bounds__(512) prep_sort_kernel()
{
    __shared__ int hist[SLEN + 1];
    __shared__ int start[SLEN + 1];
    int tid = threadIdx.x;
    for (int i = tid; i <= SLEN; i += 512) hist[i] = 0;
    __syncthreads();
    for (int b = tid; b < BSZ; b += 512) atomicAdd(&hist[g_len[b]], 1);
    __syncthreads();
    if (tid == 0) {
        int acc = 0;
        for (int L = SLEN; L >= 0; --L) { start[L] = acc; acc += hist[L]; }
    }
    __syncthreads();
    for (int b = tid; b < BSZ; b += 512) {
        int p = atomicAdd(&start[g_len[b]], 1);
        g_order[p] = b;
    }
}

// One unified recurrence step. All 128 threads call this in lockstep.
#define USTEP(XC, STP) do {                                                 \
    int par_ = (STP) & 1;                                                   \
    float* buf_ = sbuf[dir][par_];                                          \
    volatile float* msl_ = &smv[dir][par_];                                 \
    float w_, val_;                                                         \
    if (isFwd) { w_ = r; val_ = ex2f(r - m); }                              \
    else { w_ = fmaf((XC), LOG2E, r); val_ = ex2f(w_ - m); }                \
    if (act) buf_[sg] = val_;                                               \
    if (owner0) *msl_ = w_;                                                 \
    __syncthreads();                                                        \
    float s_ = matvec50_1(buf_, E);                                         \
    float mu_ = m;                                                          \
    m = *msl_;                                                              \
    if (act && (STP) <= mySteps)                                            \
        r = isFwd ? fmaf((XC), LOG2E, mu_ + lg2f(s_)) : (mu_ + lg2f(s_));   \
} while (0)

// ---------- main: persistent blocks (5/SM), 4 warps per row ----------
__global__ void __launch_bounds__(128, NBLK) crf_main_kernel(
    const float* __restrict__ x,      // [BSZ, SLEN, NC]
    const float* __restrict__ T,      // [NC, NC]
    const int* __restrict__ tags,     // [BSZ, SLEN]
    float* __restrict__ out, int out_size)
{
    __shared__ float sT[NC * NC];
    __shared__ __align__(16) float sbuf[2][2][56];   // [dir][parity][state]
    __shared__ float smv[2][2];                       // m slots [dir][parity]
    __shared__ int stags[SLEN];
    __shared__ float shalf[2][52];                    // alpha_mid / beta_mid
    __shared__ float subs[4];
    __shared__ int srow;

    const int tid = threadIdx.x;
    const int wid = tid >> 5;          // 0,1 fwd; 2,3 bwd
    const int lane = tid & 31;
    const int dir = wid >> 1;          // 0 fwd, 1 bwd
    const int half = wid & 1;          // state chunk
    const bool act = (lane < 25);
    const int sg = half * 25 + lane;   // state owned by this lane (0..49)
    const bool owner0 = (half == 0) && (lane == 0);   // owns state 0
    const bool isFwd = (dir == 0);

    for (int i = tid; i < NC * NC; i += 128) sT[i] = T[i];
    __syncthreads();

    // E built once. fwd: column sg of exp2(T*log2e), packed over c1 pairs;
    // bwd: row sg, packed over c' pairs. 25 ull = 50 regs.
    ull E[25];
    #pragma unroll
    for (int i = 0; i < 25; ++i) {
        float e0 = 0.f, e1 = 0.f;
        if (act) {
            if (isFwd) {
                e0 = ex2f(sT[(2 * i) * NC + sg] * LOG2E);
                e1 = ex2f(sT[(2 * i + 1) * NC + sg] * LOG2E);
            } else {
                e0 = ex2f(sT[sg * NC + 2 * i] * LOG2E);
                e1 = ex2f(sT[sg * NC + 2 * i + 1] * LOG2E);
            }
        }
        E[i] = pack2(e0, e1);
    }

    while (true) {
        if (tid == 0) {
            unsigned int idx = atomicAdd(&g_head, 1u);
            srow = (idx < BSZ) ? g_order[idx] : -1;
        }
        __syncthreads();
        const int row = srow;
        if (row < 0) break;
        const int len = g_len[row];        // in [128, 512]
        const int mid = (len - 1) >> 1;
        const int S = len - 1 - mid;       // bwd steps; S >= mid, S >= 63
        const int mySteps = isFwd ? mid : S;
        const float* xrow = x + (size_t)row * SLEN * NC;

        const int* trow = tags + (size_t)row * SLEN;
        for (int i = tid; i < len; i += 128) stags[i] = trow[i];
        __syncthreads();

        // unary + binary split across all 128 threads
        float ub = 0.f;
        for (int t = tid; t < len; t += 128) {
            int tg = stags[t];
            ub += __ldg(xrow + (size_t)t * NC + tg);
            if (t > 0) ub += sT[stags[t - 1] * NC + tg];
        }
        #pragma unroll
        for (int o = 16; o; o >>= 1)
            ub += __shfl_xor_sync(0xffffffffu, ub, o);
        if (lane == 0) subs[wid] = ub;

        // ---- unified recurrence: S lockstep steps, fwd pads <=1 step ----
        // fwd step s consumes x[s]; bwd step s consumes x[len-s].
        const float* xp;
        int str;
        float r, m;
        if (isFwd) {
            xp = xrow + sg;
            str = NC;
            r = act ? __ldg(xrow + sg) * LOG2E : -INFINITY;   // alpha_0
            m = __ldg(xrow) * LOG2E;                          // alpha_0[0]
        } else {
            xp = xrow + sg + (size_t)len * NC;
            str = -NC;
            r = act ? 0.f : -INFINITY;                        // beta_{len-1}
            m = __ldg(xrow + (size_t)(len - 1) * NC) * LOG2E; // w_0[0]
        }

        float x1 = 0.f, x2 = 0.f, x3 = 0.f, x4 = 0.f;
        if (act) {
            x1 = __ldg(xp + 1 * str);
            x2 = __ldg(xp + 2 * str);
            x3 = __ldg(xp + 3 * str);
            x4 = __ldg(xp + 4 * str);
        }

        int s = 1;
        for (; s + 7 <= S; s += 4) {
            float n1 = 0.f, n2 = 0.f, n3 = 0.f, n4 = 0.f;
            if (act) {
                n1 = __ldg(xp + (s + 4) * str);
                n2 = __ldg(xp + (s + 5) * str);
                n3 = __ldg(xp + (s + 6) * str);
                n4 = __ldg(xp + (s + 7) * str);
            }
            USTEP(x1, s);
            USTEP(x2, s + 1);
            USTEP(x3, s + 2);
            USTEP(x4, s + 3);
            x1 = n1; x2 = n2; x3 = n3; x4 = n4;
        }
        // remaining S - s + 1 in [4,7] (S >= 63 guarantees main loop ran)
        USTEP(x1, s);
        USTEP(x2, s + 1);
        USTEP(x3, s + 2);
        USTEP(x4, s + 3);
        for (int u = s + 4; u <= S; ++u) {
            float xd = act ? __ldg(xp + u * str) : 0.f;
            USTEP(xd, u);
        }

        if (act) shalf[dir][sg] = r;      // alpha_mid / beta_mid
        __syncthreads();

        if (wid == 0) {
            // logZ = lse_c(alpha_mid[c] + beta_mid[c]), log2 domain
            float g0 = act ? shalf[0][lane] + shalf[1][lane] : -INFINITY;
            float g1 = act ? shalf[0][lane + 25] + shalf[1][lane + 25]
                           : -INFINITY;
            float mx = fmaxf(g0, g1);
            #pragma unroll
            for (int o = 16; o; o >>= 1)
                mx = fmaxf(mx, __shfl_xor_sync(0xffffffffu, mx, o));
            float es = ex2f(g0 - mx) + ex2f(g1 - mx);
            #pragma unroll
            for (int o = 16; o; o >>= 1)
                es += __shfl_xor_sync(0xffffffffu, es, o);
            float log_norm = LN2 * (mx + lg2f(es));

            unsigned int ticket = 0;
            if (lane == 0) {
                g_partial[row] = subs[0] + subs[1] + subs[2] + subs[3]
                                 - log_norm;
                __threadfence();
                ticket = atomicAdd(&g_count, 1u);
            }
            ticket = __shfl_sync(0xffffffffu, ticket, 0);
            if (ticket == BSZ - 1) {
                __threadfence();
                float sm2 = 0.f;
                for (int i = lane; i < BSZ; i += 32) sm2 += g_partial[i];
                #pragma unroll
                for (int o = 16; o; o >>= 1)
                    sm2 += __shfl_xor_sync(0xffffffffu, sm2, o);
                if (lane == 0) out[0] = -sm2 / (float)BSZ;
                if (out_size >= 1 + NC * NC) {
                    for (int i = lane; i < NC * NC; i += 32)
                        out[1 + i] = sT[i];
                }
            }
        }
        __syncthreads();   // protect shared state for next queue pop
    }
}

extern "C" void kernel_launch(void* const* d_in, const int* in_sizes, int n_in,
                              void* d_out, int out_size) {
    const float* x = (const float*)d_in[0];
    const float* T = (const float*)d_in[1];
    const int* maskI = (const int*)d_in[2];   // bool shipped as int32
    const int* tags = (const int*)d_in[3];
    float* out = (float*)d_out;
    (void)in_sizes; (void)n_in;

    prep_len_kernel<<<128, 256>>>(maskI);
    prep_sort_kernel<<<1, 512>>>();
    crf_main_kernel<<<GRID_MAIN, 128>>>(x, T, tags, out, out_size);
}